// round 1
// baseline (speedup 1.0000x reference)
#include <cuda_runtime.h>
#include <math.h>

#define HID 512
#define NH 8
#define DD 64
#define GG 64
#define MAXN 100000
#define EPS 1e-5f

// ---- scratch (static device globals; no allocation in kernel_launch) ----
__device__ float g_w[(size_t)NH * MAXN * GG];   // slice weights  (H, N, G)
__device__ float g_y[(size_t)MAXN * HID];       // unpooled tokens before out proj
__device__ float g_tokens[NH * GG * DD];        // pooled slice tokens (pre-norm)
__device__ float g_norm[NH * GG];               // sum of w over tokens
__device__ float g_ot[NH * GG * DD];            // out_tok after slice attention

// ---------------------------------------------------------------------------
__global__ void k_zero() {
    int i = blockIdx.x * blockDim.x + threadIdx.x;
    if (i < NH * GG * DD) g_tokens[i] = 0.f;
    if (i < NH * GG) g_norm[i] = 0.f;
}

// ---------------------------------------------------------------------------
// Kernel 1: per (token-tile of 64, head h):
//   xm[64x64] = x_tile @ Wx_h^T + bx_h   (K=512 GEMM)
//   logits    = xm @ Ws^T + bs, scaled by temperature[h]
//   w         = softmax over G, written to g_w
__global__ __launch_bounds__(256) void k_proj_w(
    const float* __restrict__ x, const float* __restrict__ Wx,
    const float* __restrict__ bx, const float* __restrict__ Ws,
    const float* __restrict__ bs, const float* __restrict__ temp, int n)
{
    __shared__ float As[32][65];   // As[k][i]  (x tile, transposed)
    __shared__ float Bs[32][65];   // Bs[k][j]  (Wx_h tile)
    __shared__ float xs[64][65];   // xm staged
    __shared__ float wss[64][65];  // Ws staged

    int h = blockIdx.y;
    int row0 = blockIdx.x * 64;
    int tid = threadIdx.x;
    int warp = tid >> 5, lane = tid & 31;
    int ti = tid >> 4, tj = tid & 15;
    int i0 = ti * 4, j0 = tj * 4;
    const float* Wh = Wx + (size_t)h * 64 * HID;

    for (int e = tid; e < 64 * 64; e += 256)
        wss[e >> 6][e & 63] = Ws[e];

    float acc[4][4] = {};
    for (int k0 = 0; k0 < HID; k0 += 32) {
        for (int i = warp; i < 64; i += 8) {
            int r = row0 + i;
            As[lane][i] = (r < n) ? x[(size_t)r * HID + k0 + lane] : 0.f;
        }
        for (int j = warp; j < 64; j += 8)
            Bs[lane][j] = Wh[(size_t)j * HID + k0 + lane];
        __syncthreads();
#pragma unroll
        for (int k = 0; k < 32; ++k) {
            float a[4], b[4];
#pragma unroll
            for (int r = 0; r < 4; ++r) a[r] = As[k][i0 + r];
#pragma unroll
            for (int c = 0; c < 4; ++c) b[c] = Bs[k][j0 + c];
#pragma unroll
            for (int r = 0; r < 4; ++r)
#pragma unroll
                for (int c = 0; c < 4; ++c)
                    acc[r][c] = fmaf(a[r], b[c], acc[r][c]);
        }
        __syncthreads();
    }
#pragma unroll
    for (int r = 0; r < 4; ++r)
#pragma unroll
        for (int c = 0; c < 4; ++c)
            xs[i0 + r][j0 + c] = acc[r][c] + bx[h * 64 + j0 + c];
    __syncthreads();

    // logits + softmax: thread owns row nn = tid>>2, segment seg = tid&3 (16 g)
    int nn = tid >> 2, seg = tid & 3;
    float t = temp[h];
    float lg[16];
    float mx = -1e30f;
#pragma unroll
    for (int gi = 0; gi < 16; ++gi) {
        int g = seg * 16 + gi;
        float s = 0.f;
#pragma unroll
        for (int d = 0; d < 64; ++d) s = fmaf(xs[nn][d], wss[g][d], s);
        s = (s + bs[g]) * t;
        lg[gi] = s;
        mx = fmaxf(mx, s);
    }
    mx = fmaxf(mx, __shfl_xor_sync(0xffffffffu, mx, 1));
    mx = fmaxf(mx, __shfl_xor_sync(0xffffffffu, mx, 2));
    float sm = 0.f;
#pragma unroll
    for (int gi = 0; gi < 16; ++gi) { lg[gi] = __expf(lg[gi] - mx); sm += lg[gi]; }
    sm += __shfl_xor_sync(0xffffffffu, sm, 1);
    sm += __shfl_xor_sync(0xffffffffu, sm, 2);
    float inv = 1.f / sm;
    int rown = row0 + nn;
    if (rown < n) {
        float* wp = g_w + ((size_t)h * n + rown) * GG + seg * 16;
#pragma unroll
        for (int gi = 0; gi < 16; ++gi) wp[gi] = lg[gi] * inv;
    }
}

// ---------------------------------------------------------------------------
// Kernel 2: persistent blocks per head: fx_mid GEMM + weighted pooling.
// pt[g][d] accumulated in registers across tiles; atomics once at end.
__global__ __launch_bounds__(256) void k_pool(
    const float* __restrict__ x, const float* __restrict__ Wfx,
    const float* __restrict__ bfx, int n)
{
    __shared__ float As[32][65];
    __shared__ float Bs[32][65];
    __shared__ float fxs[64][65];
    __shared__ float ws[64][65];

    int h = blockIdx.y;
    int tid = threadIdx.x;
    int warp = tid >> 5, lane = tid & 31;
    int ti = tid >> 4, tj = tid & 15;
    int i0 = ti * 4, j0 = tj * 4;          // i0 doubles as g-offset, j0 as d-offset
    const float* Wh = Wfx + (size_t)h * 64 * HID;
    int ntiles = (n + 63) >> 6;

    float pt[4][4] = {};   // tokens partial: [g][d]
    float nm[4] = {};      // norm partial for g = i0..i0+3 over n-seg [j0..j0+3]

    for (int tile = blockIdx.x; tile < ntiles; tile += gridDim.x) {
        int row0 = tile * 64;
        float acc[4][4] = {};
        for (int k0 = 0; k0 < HID; k0 += 32) {
            for (int i = warp; i < 64; i += 8) {
                int r = row0 + i;
                As[lane][i] = (r < n) ? x[(size_t)r * HID + k0 + lane] : 0.f;
            }
            for (int j = warp; j < 64; j += 8)
                Bs[lane][j] = Wh[(size_t)j * HID + k0 + lane];
            __syncthreads();
#pragma unroll
            for (int k = 0; k < 32; ++k) {
                float a[4], b[4];
#pragma unroll
                for (int r = 0; r < 4; ++r) a[r] = As[k][i0 + r];
#pragma unroll
                for (int c = 0; c < 4; ++c) b[c] = Bs[k][j0 + c];
#pragma unroll
                for (int r = 0; r < 4; ++r)
#pragma unroll
                    for (int c = 0; c < 4; ++c)
                        acc[r][c] = fmaf(a[r], b[c], acc[r][c]);
            }
            __syncthreads();
        }
#pragma unroll
        for (int r = 0; r < 4; ++r)
#pragma unroll
            for (int c = 0; c < 4; ++c)
                fxs[i0 + r][j0 + c] = acc[r][c] + bfx[h * 64 + j0 + c];
        for (int e = tid; e < 64 * 64; e += 256) {
            int i = e >> 6, g = e & 63;
            int r = row0 + i;
            ws[i][g] = (r < n) ? g_w[((size_t)h * n + r) * GG + g] : 0.f;
        }
        __syncthreads();
#pragma unroll
        for (int nn = 0; nn < 64; ++nn) {
            float a[4], b[4];
#pragma unroll
            for (int r = 0; r < 4; ++r) a[r] = ws[nn][i0 + r];
#pragma unroll
            for (int c = 0; c < 4; ++c) b[c] = fxs[nn][j0 + c];
#pragma unroll
            for (int r = 0; r < 4; ++r)
#pragma unroll
                for (int c = 0; c < 4; ++c)
                    pt[r][c] = fmaf(a[r], b[c], pt[r][c]);
        }
#pragma unroll
        for (int gr = 0; gr < 4; ++gr) {
            float s = 0.f;
#pragma unroll
            for (int q = 0; q < 4; ++q) s += ws[j0 + q][i0 + gr];
            nm[gr] += s;
        }
        __syncthreads();
    }

    float* tk = g_tokens + h * GG * DD;
#pragma unroll
    for (int r = 0; r < 4; ++r)
#pragma unroll
        for (int c = 0; c < 4; ++c)
            atomicAdd(&tk[(i0 + r) * DD + j0 + c], pt[r][c]);

    // norm reduction in smem (reuse ws), one atomic per g per block
    __syncthreads();
#pragma unroll
    for (int gr = 0; gr < 4; ++gr) ws[i0 + gr][tj] = nm[gr];
    __syncthreads();
    if (tid < 64) {
        float s = 0.f;
#pragma unroll
        for (int q = 0; q < 16; ++q) s += ws[tid][q];
        atomicAdd(&g_norm[h * GG + tid], s);
    }
}

// ---------------------------------------------------------------------------
// Kernel 3: slice attention per head (tiny: G=64 tokens, D=64).
__global__ __launch_bounds__(64) void k_attn(
    const float* __restrict__ Wq, const float* __restrict__ Wk,
    const float* __restrict__ Wv, const float* __restrict__ Wo)
{
    __shared__ float tok[64][65];
    __shared__ float qs[64][65];
    __shared__ float ks[64][65];
    __shared__ float vs[64][65];
    __shared__ float ss[64][65];

    int h = blockIdx.x;
    int g = threadIdx.x;

    float invn = 1.f / (g_norm[h * GG + g] + EPS);
#pragma unroll 8
    for (int d = 0; d < 64; ++d)
        tok[g][d] = g_tokens[h * GG * DD + g * DD + d] * invn;
    __syncthreads();

    // q/k/v projections (W stored (out,in): q[g][o] = sum_d tok[g][d]*Wq[o][d])
    for (int o = 0; o < 64; ++o) {
        float sq = 0.f, sk = 0.f, sv = 0.f;
#pragma unroll 8
        for (int d = 0; d < 64; ++d) {
            float tv = tok[g][d];
            sq = fmaf(tv, Wq[o * 64 + d], sq);
            sk = fmaf(tv, Wk[o * 64 + d], sk);
            sv = fmaf(tv, Wv[o * 64 + d], sv);
        }
        qs[g][o] = sq; ks[g][o] = sk; vs[g][o] = sv;
    }
    __syncthreads();

    // scores + softmax over keys
    float mx = -1e30f;
    for (int j = 0; j < 64; ++j) {
        float t = 0.f;
#pragma unroll 8
        for (int o = 0; o < 64; ++o) t = fmaf(qs[g][o], ks[j][o], t);
        t *= 0.125f;   // 1/sqrt(64)
        ss[g][j] = t;
        mx = fmaxf(mx, t);
    }
    float sum = 0.f;
    for (int j = 0; j < 64; ++j) {
        float e = __expf(ss[g][j] - mx);
        ss[g][j] = e;
        sum += e;
    }
    float inv = 1.f / sum;
    __syncthreads();  // everyone done reading qs/ks and tok before reuse

    // o1 = attn @ v, stored into tok (reused)
    for (int d = 0; d < 64; ++d) {
        float t = 0.f;
#pragma unroll 8
        for (int j = 0; j < 64; ++j) t = fmaf(ss[g][j], vs[j][d], t);
        tok[g][d] = t * inv;
    }
    // out_tok = o1 @ Wo^T  (own row only, no sync needed)
    for (int o = 0; o < 64; ++o) {
        float t = 0.f;
#pragma unroll 8
        for (int d = 0; d < 64; ++d) t = fmaf(tok[g][d], Wo[o * 64 + d], t);
        g_ot[h * GG * DD + g * DD + o] = t;
    }
}

// ---------------------------------------------------------------------------
// Kernel 4: unpool: y[n][h*64+d] = sum_g out_tok[h][g][d] * w[h][n][g]
__global__ __launch_bounds__(256) void k_y(int n) {
    __shared__ float ots[64][65];
    __shared__ float ws2[128][65];

    int h = blockIdx.y;
    int row0 = blockIdx.x * 128;
    int tid = threadIdx.x;

    for (int e = tid; e < 64 * 64; e += 256)
        ots[e >> 6][e & 63] = g_ot[h * GG * DD + e];
    for (int e = tid; e < 128 * 64; e += 256) {
        int i = e >> 6, g = e & 63;
        int r = row0 + i;
        ws2[i][g] = (r < n) ? g_w[((size_t)h * n + r) * GG + g] : 0.f;
    }
    __syncthreads();

    int n0 = (tid >> 3) * 4;
    int d0 = (tid & 7) * 8;
    float acc[4][8] = {};
#pragma unroll
    for (int g = 0; g < 64; ++g) {
        float a[4], b[8];
#pragma unroll
        for (int r = 0; r < 4; ++r) a[r] = ws2[n0 + r][g];
#pragma unroll
        for (int c = 0; c < 8; ++c) b[c] = ots[g][d0 + c];
#pragma unroll
        for (int r = 0; r < 4; ++r)
#pragma unroll
            for (int c = 0; c < 8; ++c)
                acc[r][c] = fmaf(a[r], b[c], acc[r][c]);
    }
#pragma unroll
    for (int r = 0; r < 4; ++r) {
        int row = row0 + n0 + r;
        if (row < n) {
            float* yp = g_y + (size_t)row * HID + h * 64 + d0;
#pragma unroll
            for (int c = 0; c < 8; ++c) yp[c] = acc[r][c];
        }
    }
}

// ---------------------------------------------------------------------------
// Kernel 5: out = y @ Wout^T + bout   (tiled SGEMM, 64x64 tiles)
__global__ __launch_bounds__(256) void k_out(
    const float* __restrict__ Wout, const float* __restrict__ bout,
    float* __restrict__ out, int n)
{
    __shared__ float As[32][65];
    __shared__ float Bs[32][65];

    int row0 = blockIdx.x * 64;
    int jg0 = blockIdx.y * 64;
    int tid = threadIdx.x;
    int warp = tid >> 5, lane = tid & 31;
    int ti = tid >> 4, tj = tid & 15;
    int i0 = ti * 4, j0 = tj * 4;

    float acc[4][4] = {};
    for (int k0 = 0; k0 < HID; k0 += 32) {
        for (int i = warp; i < 64; i += 8) {
            int r = row0 + i;
            As[lane][i] = (r < n) ? g_y[(size_t)r * HID + k0 + lane] : 0.f;
        }
        for (int j = warp; j < 64; j += 8)
            Bs[lane][j] = Wout[(size_t)(jg0 + j) * HID + k0 + lane];
        __syncthreads();
#pragma unroll
        for (int k = 0; k < 32; ++k) {
            float a[4], b[4];
#pragma unroll
            for (int r = 0; r < 4; ++r) a[r] = As[k][i0 + r];
#pragma unroll
            for (int c = 0; c < 4; ++c) b[c] = Bs[k][j0 + c];
#pragma unroll
            for (int r = 0; r < 4; ++r)
#pragma unroll
                for (int c = 0; c < 4; ++c)
                    acc[r][c] = fmaf(a[r], b[c], acc[r][c]);
        }
        __syncthreads();
    }
#pragma unroll
    for (int r = 0; r < 4; ++r) {
        int row = row0 + i0 + r;
        if (row < n) {
#pragma unroll
            for (int c = 0; c < 4; ++c)
                out[(size_t)row * HID + jg0 + j0 + c] = acc[r][c] + bout[jg0 + j0 + c];
        }
    }
}

// ---------------------------------------------------------------------------
extern "C" void kernel_launch(void* const* d_in, const int* in_sizes, int n_in,
                              void* d_out, int out_size) {
    const float* x    = (const float*)d_in[0];
    const float* Wx   = (const float*)d_in[1];
    const float* bx   = (const float*)d_in[2];
    const float* Wfx  = (const float*)d_in[3];
    const float* bfx  = (const float*)d_in[4];
    const float* Ws   = (const float*)d_in[5];
    const float* bs   = (const float*)d_in[6];
    const float* temp = (const float*)d_in[7];
    const float* Wq   = (const float*)d_in[8];
    const float* Wk   = (const float*)d_in[9];
    const float* Wv   = (const float*)d_in[10];
    const float* Wo   = (const float*)d_in[11];
    const float* Wout = (const float*)d_in[12];
    const float* bout = (const float*)d_in[13];
    float* out = (float*)d_out;

    int n = in_sizes[0] / HID;
    int ntiles = (n + 63) / 64;

    k_zero<<<(NH * GG * DD + 255) / 256, 256>>>();

    dim3 g1(ntiles, NH);
    k_proj_w<<<g1, 256>>>(x, Wx, bx, Ws, bs, temp, n);

    dim3 g2(128, NH);
    k_pool<<<g2, 256>>>(x, Wfx, bfx, n);

    k_attn<<<NH, 64>>>(Wq, Wk, Wv, Wo);

    dim3 g3((n + 127) / 128, NH);
    k_y<<<g3, 256>>>(n);

    dim3 g4(ntiles, HID / 64);
    k_out<<<g4, 256>>>(Wout, bout, out, n);
}

// round 3
// speedup vs baseline: 4.7804x; 4.7804x over previous
#include <cuda_runtime.h>
#include <cstdint>
#include <math.h>

#define HID 512
#define NH 8
#define DD 64
#define GG 64
#define MAXN 100000
#define EPS 1e-5f

// ---------------- scratch (device globals; no runtime allocation) ----------
__device__ float g_lf[(size_t)MAXN * 1024];   // [n][0:512)=scaled logits, [512:1024)=fx_mid
__device__ float g_w[(size_t)MAXN * 512];     // softmax weights, layout [n][h*64+g]
__device__ float g_tokens[NH * GG * DD];      // pooled slice tokens (pre-norm)
__device__ float g_norm[NH * GG];
__device__ float g_ot[NH * GG * DD];          // out_tok after slice attention
__device__ float g_Wls[512 * 512];            // folded logits weights (h*64+g, k)
__device__ float g_bls[512];                  // folded logits bias
__device__ float g_P[512 * 512];              // folded unpool+outproj weights (o, h*64+g)

// ---------------- helpers ---------------------------------------------------
__device__ __forceinline__ uint32_t smem_u32(const void* p) {
    uint32_t a;
    asm("{ .reg .u64 t; cvta.to.shared.u64 t, %1; cvt.u32.u64 %0, t; }" : "=r"(a) : "l"(p));
    return a;
}
__device__ __forceinline__ uint32_t f2tf32(float f) {
    uint32_t u; asm("cvt.rna.tf32.f32 %0, %1;" : "=r"(u) : "f"(f)); return u;
}
__device__ __forceinline__ void cp_async16(uint32_t dst, const void* src, int sz) {
    asm volatile("cp.async.ca.shared.global [%0], [%1], 16, %2;"
                 :: "r"(dst), "l"(src), "r"(sz));
}
__device__ __forceinline__ void cp_commit() {
    asm volatile("cp.async.commit_group;" ::: "memory");
}
template <int N>
__device__ __forceinline__ void cp_wait() {
    asm volatile("cp.async.wait_group %0;" :: "n"(N) : "memory");
}
__device__ __forceinline__ void mma_tf32(float* c, uint32_t a0, uint32_t a1,
                                         uint32_t a2, uint32_t a3,
                                         uint32_t b0, uint32_t b1) {
    asm volatile(
        "mma.sync.aligned.m16n8k8.row.col.f32.tf32.tf32.f32 "
        "{%0,%1,%2,%3}, {%4,%5,%6,%7}, {%8,%9}, {%0,%1,%2,%3};"
        : "+f"(c[0]), "+f"(c[1]), "+f"(c[2]), "+f"(c[3])
        : "r"(a0), "r"(a1), "r"(a2), "r"(a3), "r"(b0), "r"(b1));
}

// ---------------------------------------------------------------------------
__global__ void k_zero() {
    int i = blockIdx.x * blockDim.x + threadIdx.x;
    if (i < NH * GG * DD) g_tokens[i] = 0.f;
    if (i < NH * GG) g_norm[i] = 0.f;
}

// ---------------------------------------------------------------------------
// prep1: Wls[h*64+g][k] = t[h] * sum_d Ws[g][d]*Wx[h*64+d][k]
//        bls[h*64+g]    = t[h] * (sum_d Ws[g][d]*bx[h*64+d] + bs[g])
__global__ __launch_bounds__(256) void k_prep1(
    const float* __restrict__ Wx, const float* __restrict__ bx,
    const float* __restrict__ Ws, const float* __restrict__ bs,
    const float* __restrict__ temp)
{
    __shared__ float Wss[64][64];
    __shared__ float Wxs[64][128];
    int kb = blockIdx.x, h = blockIdx.y;
    int tid = threadIdx.x;
    for (int e = tid; e < 64 * 64; e += 256) Wss[e >> 6][e & 63] = Ws[e];
    for (int e = tid; e < 64 * 128; e += 256) {
        int d = e >> 7, k = e & 127;
        Wxs[d][k] = Wx[(size_t)(h * 64 + d) * HID + kb * 128 + k];
    }
    __syncthreads();
    int g = tid >> 2, q = tid & 3;
    float t = temp[h];
    for (int ki = 0; ki < 32; ++ki) {
        int k = q * 32 + ki;
        float s = 0.f;
#pragma unroll
        for (int d = 0; d < 64; ++d) s = fmaf(Wss[g][d], Wxs[d][k], s);
        g_Wls[(size_t)(h * 64 + g) * HID + kb * 128 + k] = t * s;
    }
    if (kb == 0 && q == 0) {
        float s = 0.f;
#pragma unroll
        for (int d = 0; d < 64; ++d) s = fmaf(Wss[g][d], bx[h * 64 + d], s);
        g_bls[h * 64 + g] = t * (s + bs[g]);
    }
}

// ---------------------------------------------------------------------------
// tf32 mma.sync GEMM: C[row][col0+j] = sum_k A[row][k]*B[j][k] + bias[j]
// block 128x128, K=512 (16 chunks of 32), cp.async double buffer.
// smem row stride 36 floats (bank-conflict-free fragment loads).
#define KCH 32
#define ASTRIDE 36
#define STAGE_F (128 * ASTRIDE)          // floats per operand per stage
#define STAGE_B (STAGE_F * 4)            // bytes
#define SMEM_GEMM (2 * 2 * STAGE_B)      // 2 stages x (A+B)

__global__ __launch_bounds__(256, 2) void k_gemm(
    const float* __restrict__ A,
    const float* __restrict__ B0, const float* __restrict__ B1,
    const float* __restrict__ bias0, const float* __restrict__ bias1,
    int splitJ, float* __restrict__ C, int ldc, int n)
{
    extern __shared__ float sm[];
    uint32_t sb = smem_u32(sm);

    int tid = threadIdx.x;
    int wid = tid >> 5, lane = tid & 31;
    int grp = lane >> 2, q = lane & 3;
    int wm = wid >> 1, wn = wid & 1;

    int row0 = blockIdx.x * 128;
    int jt = blockIdx.y;
    const float* B = (jt < splitJ) ? B0 + (size_t)jt * 128 * HID
                                   : B1 + (size_t)(jt - splitJ) * 128 * HID;
    const float* bias = (jt < splitJ) ? bias0 + jt * 128 : bias1 + (jt - splitJ) * 128;
    int col0 = jt * 128;

    float acc[2][8][4];
#pragma unroll
    for (int a = 0; a < 2; ++a)
#pragma unroll
        for (int b = 0; b < 8; ++b)
#pragma unroll
            for (int r = 0; r < 4; ++r) acc[a][b][r] = 0.f;

    // ---- copy lambda replacement: issue one stage's cp.asyncs -------------
    // slots: 0..1023 A (row=i>>3, c4=i&7), 1024..2047 B
    auto issue = [&](int c, int stg) {
        int k0 = c * KCH;
        uint32_t base = sb + stg * (2 * STAGE_B);
#pragma unroll
        for (int it = 0; it < 8; ++it) {
            int slot = tid + it * 256;
            int isB = slot >> 10;
            int sl = slot & 1023;
            int r = sl >> 3, c4 = sl & 7;
            uint32_t dst = base + isB * STAGE_B + (uint32_t)(r * (ASTRIDE * 4) + c4 * 16);
            if (!isB) {
                int gr = row0 + r;
                const float* src = A + ((gr < n) ? ((size_t)gr * HID + k0 + c4 * 4) : 0);
                cp_async16(dst, src, (gr < n) ? 16 : 0);
            } else {
                const float* src = B + (size_t)r * HID + k0 + c4 * 4;
                cp_async16(dst, src, 16);
            }
        }
        cp_commit();
    };

    issue(0, 0);

    for (int c = 0; c < 16; ++c) {
        int stg = c & 1;
        if (c < 15) {
            issue(c + 1, stg ^ 1);
            cp_wait<1>();
        } else {
            cp_wait<0>();
        }
        __syncthreads();

        const float* As = sm + stg * (2 * STAGE_F);
        const float* Bs = As + STAGE_F;
        int mbase = wm * 32;
        int nbase = wn * 64;

#pragma unroll
        for (int s = 0; s < 4; ++s) {
            int kk = s * 8 + q;
            uint32_t af[2][4];
#pragma unroll
            for (int tm = 0; tm < 2; ++tm) {
                int rr = mbase + tm * 16 + grp;
                af[tm][0] = f2tf32(As[rr * ASTRIDE + kk]);
                af[tm][1] = f2tf32(As[(rr + 8) * ASTRIDE + kk]);
                af[tm][2] = f2tf32(As[rr * ASTRIDE + kk + 4]);
                af[tm][3] = f2tf32(As[(rr + 8) * ASTRIDE + kk + 4]);
            }
#pragma unroll
            for (int nt = 0; nt < 8; ++nt) {
                int cc = nbase + nt * 8 + grp;
                uint32_t b0 = f2tf32(Bs[cc * ASTRIDE + kk]);
                uint32_t b1 = f2tf32(Bs[cc * ASTRIDE + kk + 4]);
#pragma unroll
                for (int tm = 0; tm < 2; ++tm)
                    mma_tf32(acc[tm][nt], af[tm][0], af[tm][1], af[tm][2], af[tm][3], b0, b1);
            }
        }
        __syncthreads();
    }

    // ---- epilogue ----------------------------------------------------------
#pragma unroll
    for (int tm = 0; tm < 2; ++tm) {
        int r0 = row0 + wm * 32 + tm * 16 + grp;
#pragma unroll
        for (int nt = 0; nt < 8; ++nt) {
            int cl = wn * 64 + nt * 8 + q * 2;
            float b0 = bias[cl], b1 = bias[cl + 1];
            if (r0 < n) {
                float2 v = make_float2(acc[tm][nt][0] + b0, acc[tm][nt][1] + b1);
                *reinterpret_cast<float2*>(&C[(size_t)r0 * ldc + col0 + cl]) = v;
            }
            if (r0 + 8 < n) {
                float2 v = make_float2(acc[tm][nt][2] + b0, acc[tm][nt][3] + b1);
                *reinterpret_cast<float2*>(&C[(size_t)(r0 + 8) * ldc + col0 + cl]) = v;
            }
        }
    }
}

// ---------------------------------------------------------------------------
// softmax over each 64-group of scaled logits -> g_w (layout [n][h*64+g])
__global__ __launch_bounds__(256) void k_w(int n) {
    int nidx = blockIdx.x * 8 + (threadIdx.x >> 5);
    int lane = threadIdx.x & 31;
    if (nidx >= n) return;
    const float* lp = g_lf + (size_t)nidx * 1024;
    float* wp = g_w + (size_t)nidx * 512;
#pragma unroll
    for (int h = 0; h < 8; ++h) {
        float2 v = *reinterpret_cast<const float2*>(lp + h * 64 + lane * 2);
        float mx = fmaxf(v.x, v.y);
#pragma unroll
        for (int o = 16; o > 0; o >>= 1) mx = fmaxf(mx, __shfl_xor_sync(0xffffffffu, mx, o));
        float e0 = __expf(v.x - mx), e1 = __expf(v.y - mx);
        float s = e0 + e1;
#pragma unroll
        for (int o = 16; o > 0; o >>= 1) s += __shfl_xor_sync(0xffffffffu, s, o);
        float inv = 1.f / s;
        float2 r; r.x = e0 * inv; r.y = e1 * inv;
        *reinterpret_cast<float2*>(wp + h * 64 + lane * 2) = r;
    }
}

// ---------------------------------------------------------------------------
// pooling: tokens[h][g][d] += sum_n w[n][h*64+g] * fx[n][h*64+d]; norm too.
__global__ __launch_bounds__(256) void k_pool(int n) {
    __shared__ float fxs[64][65];
    __shared__ float ws[64][65];
    int h = blockIdx.y, tid = threadIdx.x;
    int ti = tid >> 4, tj = tid & 15;
    int i0 = ti * 4, j0 = tj * 4;
    int ntiles = (n + 63) >> 6;

    float pt[4][4] = {};
    float nm[4] = {};

    for (int tile = blockIdx.x; tile < ntiles; tile += gridDim.x) {
        int row0 = tile * 64;
        for (int e = tid; e < 64 * 64; e += 256) {
            int i = e >> 6, d = e & 63;
            int r = row0 + i;
            fxs[i][d] = (r < n) ? g_lf[(size_t)r * 1024 + 512 + h * 64 + d] : 0.f;
            ws[i][d]  = (r < n) ? g_w[(size_t)r * 512 + h * 64 + d] : 0.f;
        }
        __syncthreads();
#pragma unroll
        for (int nn = 0; nn < 64; ++nn) {
            float a[4], b[4];
#pragma unroll
            for (int r = 0; r < 4; ++r) a[r] = ws[nn][i0 + r];
#pragma unroll
            for (int c = 0; c < 4; ++c) b[c] = fxs[nn][j0 + c];
#pragma unroll
            for (int r = 0; r < 4; ++r)
#pragma unroll
                for (int c = 0; c < 4; ++c)
                    pt[r][c] = fmaf(a[r], b[c], pt[r][c]);
        }
#pragma unroll
        for (int gr = 0; gr < 4; ++gr) {
            float s = 0.f;
#pragma unroll
            for (int qq = 0; qq < 4; ++qq) s += ws[j0 + qq][i0 + gr];
            nm[gr] += s;
        }
        __syncthreads();
    }

    float* tk = g_tokens + h * GG * DD;
#pragma unroll
    for (int r = 0; r < 4; ++r)
#pragma unroll
        for (int c = 0; c < 4; ++c)
            atomicAdd(&tk[(i0 + r) * DD + j0 + c], pt[r][c]);

    __syncthreads();
#pragma unroll
    for (int gr = 0; gr < 4; ++gr) ws[i0 + gr][tj] = nm[gr];
    __syncthreads();
    if (tid < 64) {
        float s = 0.f;
#pragma unroll
        for (int qq = 0; qq < 16; ++qq) s += ws[tid][qq];
        atomicAdd(&g_norm[h * GG + tid], s);
    }
}

// ---------------------------------------------------------------------------
// slice attention per head, 256 threads: thread (g = tid>>2, q = tid&3)
__global__ __launch_bounds__(256) void k_attn(
    const float* __restrict__ Wq, const float* __restrict__ Wk,
    const float* __restrict__ Wv, const float* __restrict__ Wo)
{
    __shared__ float tok[64][65];
    __shared__ float qs[64][65];
    __shared__ float ks[64][65];
    __shared__ float vs[64][65];
    __shared__ float ss[64][65];

    int h = blockIdx.x;
    int tid = threadIdx.x;
    int g = tid >> 2, q = tid & 3;

    for (int e = tid; e < 64 * 64; e += 256) {
        int gg = e >> 6, d = e & 63;
        tok[gg][d] = g_tokens[h * GG * DD + e] * (1.f / (g_norm[h * GG + gg] + EPS));
    }
    __syncthreads();

#pragma unroll
    for (int oi = 0; oi < 16; ++oi) {
        int o = q * 16 + oi;
        float sq = 0.f, sk = 0.f, sv = 0.f;
#pragma unroll
        for (int d = 0; d < 64; ++d) {
            float tv = tok[g][d];
            sq = fmaf(tv, Wq[o * 64 + d], sq);
            sk = fmaf(tv, Wk[o * 64 + d], sk);
            sv = fmaf(tv, Wv[o * 64 + d], sv);
        }
        qs[g][o] = sq; ks[g][o] = sk; vs[g][o] = sv;
    }
    __syncthreads();

    float sj[16];
    float mx = -1e30f;
#pragma unroll
    for (int ji = 0; ji < 16; ++ji) {
        int j = q * 16 + ji;
        float t = 0.f;
#pragma unroll
        for (int o = 0; o < 64; ++o) t = fmaf(qs[g][o], ks[j][o], t);
        t *= 0.125f;
        sj[ji] = t;
        mx = fmaxf(mx, t);
    }
    mx = fmaxf(mx, __shfl_xor_sync(0xffffffffu, mx, 1));
    mx = fmaxf(mx, __shfl_xor_sync(0xffffffffu, mx, 2));
    float sum = 0.f;
#pragma unroll
    for (int ji = 0; ji < 16; ++ji) { sj[ji] = __expf(sj[ji] - mx); sum += sj[ji]; }
    sum += __shfl_xor_sync(0xffffffffu, sum, 1);
    sum += __shfl_xor_sync(0xffffffffu, sum, 2);
    float inv = 1.f / sum;
#pragma unroll
    for (int ji = 0; ji < 16; ++ji) ss[g][q * 16 + ji] = sj[ji];
    __syncthreads();

#pragma unroll
    for (int di = 0; di < 16; ++di) {
        int d = q * 16 + di;
        float t = 0.f;
#pragma unroll
        for (int j = 0; j < 64; ++j) t = fmaf(ss[g][j], vs[j][d], t);
        tok[g][d] = t * inv;
    }
    __syncthreads();

#pragma unroll
    for (int oi = 0; oi < 16; ++oi) {
        int o = q * 16 + oi;
        float t = 0.f;
#pragma unroll
        for (int d = 0; d < 64; ++d) t = fmaf(tok[g][d], Wo[o * 64 + d], t);
        g_ot[h * GG * DD + g * DD + o] = t;
    }
}

// ---------------------------------------------------------------------------
// prep2: P[o][h*64+g] = sum_d Wout[o][h*64+d] * ot[h][g][d]
__global__ __launch_bounds__(256) void k_prep2(const float* __restrict__ Wout) {
    __shared__ float ots[64][65];
    int h = blockIdx.x;
    int tid = threadIdx.x;
    for (int e = tid; e < 64 * 64; e += 256)
        ots[e >> 6][e & 63] = g_ot[h * GG * DD + e];
    __syncthreads();
    for (int o = tid; o < 512; o += 256) {
        float wr[64];
#pragma unroll
        for (int d = 0; d < 64; ++d) wr[d] = Wout[(size_t)o * HID + h * 64 + d];
        for (int g = 0; g < 64; ++g) {
            float s = 0.f;
#pragma unroll
            for (int d = 0; d < 64; ++d) s = fmaf(wr[d], ots[g][d], s);
            g_P[(size_t)o * 512 + h * 64 + g] = s;
        }
    }
}

// ---------------------------------------------------------------------------
extern "C" void kernel_launch(void* const* d_in, const int* in_sizes, int n_in,
                              void* d_out, int out_size) {
    const float* x    = (const float*)d_in[0];
    const float* Wx   = (const float*)d_in[1];
    const float* bx   = (const float*)d_in[2];
    const float* Wfx  = (const float*)d_in[3];
    const float* bfx  = (const float*)d_in[4];
    const float* Ws   = (const float*)d_in[5];
    const float* bs   = (const float*)d_in[6];
    const float* temp = (const float*)d_in[7];
    const float* Wq   = (const float*)d_in[8];
    const float* Wk   = (const float*)d_in[9];
    const float* Wv   = (const float*)d_in[10];
    const float* Wo   = (const float*)d_in[11];
    const float* Wout = (const float*)d_in[12];
    const float* bout = (const float*)d_in[13];
    float* out = (float*)d_out;

    int n = in_sizes[0] / HID;
    int mtiles = (n + 127) / 128;

    float* g_lf_p;   cudaGetSymbolAddress((void**)&g_lf_p, g_lf);
    float* g_w_p;    cudaGetSymbolAddress((void**)&g_w_p, g_w);
    float* g_Wls_p;  cudaGetSymbolAddress((void**)&g_Wls_p, g_Wls);
    float* g_bls_p;  cudaGetSymbolAddress((void**)&g_bls_p, g_bls);
    float* g_P_p;    cudaGetSymbolAddress((void**)&g_P_p, g_P);

    cudaFuncSetAttribute(k_gemm, cudaFuncAttributeMaxDynamicSharedMemorySize, SMEM_GEMM);

    k_zero<<<(NH * GG * DD + 255) / 256, 256>>>();

    dim3 gp1(4, NH);
    k_prep1<<<gp1, 256>>>(Wx, bx, Ws, bs, temp);

    // GEMM1: [logits | fx_mid] = x @ [Wls ; Wfx]^T + [bls ; bfx]
    dim3 gg1(mtiles, 8);
    k_gemm<<<gg1, 256, SMEM_GEMM>>>(x, g_Wls_p, Wfx, g_bls_p, bfx, 4, g_lf_p, 1024, n);

    k_w<<<(n + 7) / 8, 256>>>(n);

    dim3 gpool(128, NH);
    k_pool<<<gpool, 256>>>(n);

    k_attn<<<NH, 256>>>(Wq, Wk, Wv, Wo);

    k_prep2<<<NH, 256>>>(Wout);

    // GEMM2: out = w_flat @ P^T + bout
    dim3 gg2(mtiles, 4);
    k_gemm<<<gg2, 256, SMEM_GEMM>>>(g_w_p, g_P_p, g_P_p, bout, bout, 4, out, 512, n);
}

// round 4
// speedup vs baseline: 8.5912x; 1.7972x over previous
#include <cuda_runtime.h>
#include <cstdint>
#include <math.h>

#define HID 512
#define NH 8
#define MAXN 100000
#define EPS 1e-5f

// ---------------- scratch (device globals; bf16 packed as u32 pairs) -------
__device__ uint32_t g_x_bf[(size_t)MAXN * 256];    // x bf16  [n][512]
__device__ uint32_t g_fx_bf[(size_t)MAXN * 256];   // fx bf16 [n][512]
__device__ uint32_t g_w_bf[(size_t)MAXN * 256];    // softmax w bf16 [n][512]
__device__ uint32_t g_Wls_bf[512 * 256];           // folded logits W bf16 [hg][512]
__device__ uint32_t g_Wfx_bf[512 * 256];           // Wfx bf16
__device__ uint32_t g_P_bf[512 * 256];             // folded unpool+outproj bf16 [o][hg]
__device__ float g_bls[512];
__device__ float g_tokens[NH * 64 * 64];
__device__ float g_norm[NH * 64];
__device__ float g_ot[NH * 64 * 64];

// ---------------- helpers ---------------------------------------------------
__device__ __forceinline__ uint32_t smem_u32(const void* p) {
    uint32_t a;
    asm("{ .reg .u64 t; cvta.to.shared.u64 t, %1; cvt.u32.u64 %0, t; }" : "=r"(a) : "l"(p));
    return a;
}
__device__ __forceinline__ uint32_t pk(float lo, float hi) {
    uint32_t r;
    asm("cvt.rn.bf16x2.f32 %0, %1, %2;" : "=r"(r) : "f"(hi), "f"(lo));
    return r;
}
__device__ __forceinline__ void cp_async16(uint32_t dst, const void* src, int sz) {
    asm volatile("cp.async.ca.shared.global [%0], [%1], 16, %2;"
                 :: "r"(dst), "l"(src), "r"(sz));
}
__device__ __forceinline__ void cp_commit() {
    asm volatile("cp.async.commit_group;" ::: "memory");
}
template <int N>
__device__ __forceinline__ void cp_wait() {
    asm volatile("cp.async.wait_group %0;" :: "n"(N) : "memory");
}
__device__ __forceinline__ void mma_bf16(float* c, uint32_t a0, uint32_t a1,
                                         uint32_t a2, uint32_t a3,
                                         uint32_t b0, uint32_t b1) {
    asm volatile(
        "mma.sync.aligned.m16n8k16.row.col.f32.bf16.bf16.f32 "
        "{%0,%1,%2,%3}, {%4,%5,%6,%7}, {%8,%9}, {%0,%1,%2,%3};"
        : "+f"(c[0]), "+f"(c[1]), "+f"(c[2]), "+f"(c[3])
        : "r"(a0), "r"(a1), "r"(a2), "r"(a3), "r"(b0), "r"(b1));
}
__device__ __forceinline__ void ldm_x4t(uint32_t* r, uint32_t addr) {
    asm volatile("ldmatrix.sync.aligned.m8n8.x4.trans.shared.b16 {%0,%1,%2,%3}, [%4];"
                 : "=r"(r[0]), "=r"(r[1]), "=r"(r[2]), "=r"(r[3]) : "r"(addr));
}
__device__ __forceinline__ void ldm_x2t(uint32_t& r0, uint32_t& r1, uint32_t addr) {
    asm volatile("ldmatrix.sync.aligned.m8n8.x2.trans.shared.b16 {%0,%1}, [%2];"
                 : "=r"(r0), "=r"(r1) : "r"(addr));
}

// ---------------------------------------------------------------------------
__global__ void k_zero() {
    int i = blockIdx.x * blockDim.x + threadIdx.x;
    if (i < NH * 64 * 64) g_tokens[i] = 0.f;
    if (i < NH * 64) g_norm[i] = 0.f;
}

// generic fp32 -> bf16 pair converter
__global__ void k_cvt(const float* __restrict__ src, uint32_t* __restrict__ dst,
                      int npairs) {
    int i = blockIdx.x * blockDim.x + threadIdx.x;
    if (i < npairs) {
        float2 v = reinterpret_cast<const float2*>(src)[i];
        dst[i] = pk(v.x, v.y);
    }
}

// ---------------------------------------------------------------------------
// prep1: Wls[hg][k] = t[h]*sum_d Ws[g][d]*Wx[h*64+d][k]  (stored bf16)
//        bls[hg]    = t[h]*(sum_d Ws[g][d]*bx[h*64+d] + bs[g])
__global__ __launch_bounds__(256) void k_prep1(
    const float* __restrict__ Wx, const float* __restrict__ bx,
    const float* __restrict__ Ws, const float* __restrict__ bs,
    const float* __restrict__ temp)
{
    __shared__ float Wss[64][64];
    __shared__ float Wxs[64][128];
    int kb = blockIdx.x, h = blockIdx.y;
    int tid = threadIdx.x;
    for (int e = tid; e < 64 * 64; e += 256) Wss[e >> 6][e & 63] = Ws[e];
    for (int e = tid; e < 64 * 128; e += 256) {
        int d = e >> 7, k = e & 127;
        Wxs[d][k] = Wx[(size_t)(h * 64 + d) * HID + kb * 128 + k];
    }
    __syncthreads();
    int g = tid >> 2, q = tid & 3;
    float t = temp[h];
    for (int ki = 0; ki < 32; ki += 2) {
        float s0 = 0.f, s1 = 0.f;
#pragma unroll
        for (int d = 0; d < 64; ++d) {
            float wv = Wss[g][d];
            s0 = fmaf(wv, Wxs[d][q * 32 + ki], s0);
            s1 = fmaf(wv, Wxs[d][q * 32 + ki + 1], s1);
        }
        g_Wls_bf[(size_t)(h * 64 + g) * 256 + kb * 64 + q * 16 + (ki >> 1)] =
            pk(t * s0, t * s1);
    }
    if (kb == 0 && q == 0) {
        float s = 0.f;
#pragma unroll
        for (int d = 0; d < 64; ++d) s = fmaf(Wss[g][d], bx[h * 64 + d], s);
        g_bls[h * 64 + g] = t * (s + bs[g]);
    }
}

// ---------------------------------------------------------------------------
// bf16 mma GEMM: block 128x128, K=512 (8 chunks of 64), cp.async 2-stage.
// smem row stride 72 halves (conflict-free fragment LDS).
// mode 0: C = A@B^T + bias (fp32 out)
// mode 1: jt<splitJ -> temperature-softmax epilogue -> g_w_bf
//         jt>=splitJ -> +bias -> g_fx_bf
#define SH 72
#define STAGE_B2 (128 * SH * 2)              // 18432 bytes per operand stage
#define SMEM_GEMM (2 * 2 * STAGE_B2)         // 73728

__global__ __launch_bounds__(256, 2) void k_gemm(
    const uint16_t* __restrict__ A,
    const uint16_t* __restrict__ B0, const uint16_t* __restrict__ B1,
    const float* __restrict__ bias0, const float* __restrict__ bias1,
    int splitJ, int mode, float* __restrict__ Cf, int ldc, int n)
{
    extern __shared__ __align__(16) unsigned char smraw[];
    uint32_t sb = smem_u32(smraw);
    uint32_t* smw = reinterpret_cast<uint32_t*>(smraw);

    int tid = threadIdx.x;
    int wid = tid >> 5, lane = tid & 31;
    int grp = lane >> 2, q = lane & 3;
    int wm = wid >> 1, wn = wid & 1;

    int row0 = blockIdx.x * 128;
    int jt = blockIdx.y;
    const uint16_t* B = (jt < splitJ) ? B0 + (size_t)jt * 128 * HID
                                      : B1 + (size_t)(jt - splitJ) * 128 * HID;
    int col0 = jt * 128;

    float acc[2][8][4];
#pragma unroll
    for (int a = 0; a < 2; ++a)
#pragma unroll
        for (int b = 0; b < 8; ++b)
#pragma unroll
            for (int r = 0; r < 4; ++r) acc[a][b][r] = 0.f;

    auto issue = [&](int c, int stg) {
        int k0 = c * 64;
        uint32_t base = sb + stg * (2 * STAGE_B2);
#pragma unroll
        for (int it = 0; it < 8; ++it) {
            int slot = tid + it * 256;       // 0..2047
            int isB = slot >> 10;
            int sl = slot & 1023;
            int r = sl >> 3, c4 = sl & 7;    // 8 halves per granule
            uint32_t dst = base + isB * STAGE_B2 + (uint32_t)(r * (SH * 2) + c4 * 16);
            if (!isB) {
                int gr = row0 + r;
                const uint16_t* src = A + ((gr < n) ? ((size_t)gr * HID + k0 + c4 * 8) : 0);
                cp_async16(dst, src, (gr < n) ? 16 : 0);
            } else {
                cp_async16(dst, B + (size_t)r * HID + k0 + c4 * 8, 16);
            }
        }
        cp_commit();
    };

    issue(0, 0);

    for (int c = 0; c < 8; ++c) {
        int stg = c & 1;
        if (c < 7) { issue(c + 1, stg ^ 1); cp_wait<1>(); }
        else       { cp_wait<0>(); }
        __syncthreads();

        const uint32_t* Asw = smw + stg * (STAGE_B2 / 2);  // u32 words
        const uint32_t* Bsw = Asw + (STAGE_B2 / 4);
        int mbase = wm * 32, nbase = wn * 64;

#pragma unroll
        for (int s = 0; s < 4; ++s) {
            int kw = s * 8;  // word offset (16 halves)
            uint32_t af[2][4];
#pragma unroll
            for (int tm = 0; tm < 2; ++tm) {
                int rr = mbase + tm * 16 + grp;
                af[tm][0] = Asw[rr * 36 + kw + q];
                af[tm][1] = Asw[(rr + 8) * 36 + kw + q];
                af[tm][2] = Asw[rr * 36 + kw + 4 + q];
                af[tm][3] = Asw[(rr + 8) * 36 + kw + 4 + q];
            }
#pragma unroll
            for (int nt = 0; nt < 8; ++nt) {
                int cc = nbase + nt * 8 + grp;
                uint32_t b0 = Bsw[cc * 36 + kw + q];
                uint32_t b1 = Bsw[cc * 36 + kw + 4 + q];
#pragma unroll
                for (int tm = 0; tm < 2; ++tm)
                    mma_bf16(acc[tm][nt], af[tm][0], af[tm][1], af[tm][2], af[tm][3], b0, b1);
            }
        }
        __syncthreads();
    }

    // ---- epilogue ----------------------------------------------------------
    const float* bias = (jt < splitJ) ? bias0 + jt * 128 : bias1 + (jt - splitJ) * 128;

    if (mode == 0) {
#pragma unroll
        for (int tm = 0; tm < 2; ++tm) {
            int r0 = row0 + wm * 32 + tm * 16 + grp;
#pragma unroll
            for (int nt = 0; nt < 8; ++nt) {
                int cl = wn * 64 + nt * 8 + q * 2;
                float b0 = bias[cl], b1 = bias[cl + 1];
                if (r0 < n) {
                    float2 v = make_float2(acc[tm][nt][0] + b0, acc[tm][nt][1] + b1);
                    *reinterpret_cast<float2*>(&Cf[(size_t)r0 * ldc + col0 + cl]) = v;
                }
                if (r0 + 8 < n) {
                    float2 v = make_float2(acc[tm][nt][2] + b0, acc[tm][nt][3] + b1);
                    *reinterpret_cast<float2*>(&Cf[(size_t)(r0 + 8) * ldc + col0 + cl]) = v;
                }
            }
        }
        return;
    }

    // mode 1
    if (jt < splitJ) {
        // temperature-softmax over the 64-col group (whole group lives in this warp quad)
#pragma unroll
        for (int tm = 0; tm < 2; ++tm) {
            float mx0 = -1e30f, mx1 = -1e30f;
#pragma unroll
            for (int nt = 0; nt < 8; ++nt) {
                int cl = wn * 64 + nt * 8 + q * 2;
                float b0 = bias[cl], b1 = bias[cl + 1];
                acc[tm][nt][0] += b0; acc[tm][nt][1] += b1;
                acc[tm][nt][2] += b0; acc[tm][nt][3] += b1;
                mx0 = fmaxf(mx0, fmaxf(acc[tm][nt][0], acc[tm][nt][1]));
                mx1 = fmaxf(mx1, fmaxf(acc[tm][nt][2], acc[tm][nt][3]));
            }
            mx0 = fmaxf(mx0, __shfl_xor_sync(0xffffffffu, mx0, 1));
            mx0 = fmaxf(mx0, __shfl_xor_sync(0xffffffffu, mx0, 2));
            mx1 = fmaxf(mx1, __shfl_xor_sync(0xffffffffu, mx1, 1));
            mx1 = fmaxf(mx1, __shfl_xor_sync(0xffffffffu, mx1, 2));
            float s0 = 0.f, s1 = 0.f;
#pragma unroll
            for (int nt = 0; nt < 8; ++nt) {
                acc[tm][nt][0] = __expf(acc[tm][nt][0] - mx0);
                acc[tm][nt][1] = __expf(acc[tm][nt][1] - mx0);
                acc[tm][nt][2] = __expf(acc[tm][nt][2] - mx1);
                acc[tm][nt][3] = __expf(acc[tm][nt][3] - mx1);
                s0 += acc[tm][nt][0] + acc[tm][nt][1];
                s1 += acc[tm][nt][2] + acc[tm][nt][3];
            }
            s0 += __shfl_xor_sync(0xffffffffu, s0, 1);
            s0 += __shfl_xor_sync(0xffffffffu, s0, 2);
            s1 += __shfl_xor_sync(0xffffffffu, s1, 1);
            s1 += __shfl_xor_sync(0xffffffffu, s1, 2);
            float i0 = 1.f / s0, i1 = 1.f / s1;
            int r0 = row0 + wm * 32 + tm * 16 + grp;
#pragma unroll
            for (int nt = 0; nt < 8; ++nt) {
                int w32 = (col0 + wn * 64 + nt * 8 + q * 2) >> 1;
                if (r0 < n)
                    g_w_bf[(size_t)r0 * 256 + w32] =
                        pk(acc[tm][nt][0] * i0, acc[tm][nt][1] * i0);
                if (r0 + 8 < n)
                    g_w_bf[(size_t)(r0 + 8) * 256 + w32] =
                        pk(acc[tm][nt][2] * i1, acc[tm][nt][3] * i1);
            }
        }
    } else {
        // fx path: +bias, store bf16
#pragma unroll
        for (int tm = 0; tm < 2; ++tm) {
            int r0 = row0 + wm * 32 + tm * 16 + grp;
#pragma unroll
            for (int nt = 0; nt < 8; ++nt) {
                int cl = wn * 64 + nt * 8 + q * 2;
                float b0 = bias[cl], b1 = bias[cl + 1];
                int f32i = ((jt - splitJ) * 128 + cl) >> 1;
                if (r0 < n)
                    g_fx_bf[(size_t)r0 * 256 + f32i] =
                        pk(acc[tm][nt][0] + b0, acc[tm][nt][1] + b1);
                if (r0 + 8 < n)
                    g_fx_bf[(size_t)(r0 + 8) * 256 + f32i] =
                        pk(acc[tm][nt][2] + b0, acc[tm][nt][3] + b1);
            }
        }
    }
}

// ---------------------------------------------------------------------------
// pooling via bf16 mma split-K: tokens[h][g][d] = sum_n w[n][hg]*fx[n][hd];
// norm via baked ones-column (d=64). grid (32, NH), 128 threads.
#define PSH 72                      // halves per smem row (64 data + 8 pad)
#define PSTAGE (64 * PSH * 2)       // 9216 bytes per operand per stage

__global__ __launch_bounds__(128) void k_pool(int n) {
    __shared__ __align__(16) unsigned char psm[2 * 2 * PSTAGE];  // 36864
    uint32_t sb = smem_u32(psm);
    uint32_t* smw = reinterpret_cast<uint32_t*>(psm);

    int h = blockIdx.y;
    int cta = blockIdx.x;
    int tid = threadIdx.x;
    int wid = tid >> 5, lane = tid & 31;
    int grp = lane >> 2, q = lane & 3;

    int per = (((n + 31) / 32) + 63) & ~63;
    int nstart = cta * per;
    int nend = min(nstart + per, n);

    // init fx pad columns (64..71) of both stages: col64=1.0, rest 0
    // word layout per row: 36 words; pad words 32..35
    for (int i = tid; i < 2 * 64 * 4; i += 128) {
        int stg = i >> 8, rw = (i >> 2) & 63, pw = i & 3;
        uint32_t* fxs = smw + (stg * 2 * PSTAGE + PSTAGE) / 4;
        fxs[rw * 36 + 32 + pw] = (pw == 0) ? 0x00003F80u : 0u;
    }

    float acc[9][4];
#pragma unroll
    for (int a = 0; a < 9; ++a)
#pragma unroll
        for (int r = 0; r < 4; ++r) acc[a][r] = 0.f;

    int nchunks = (nend > nstart) ? ((nend - nstart + 63) >> 6) : 0;

    auto issue = [&](int c, int stg) {
        int n0 = nstart + c * 64;
        uint32_t base = sb + stg * (2 * PSTAGE);
#pragma unroll
        for (int it = 0; it < 8; ++it) {
            int slot = tid + it * 128;     // 0..1023
            int isF = slot >> 9;
            int sl = slot & 511;
            int r = sl >> 3, c8 = sl & 7;
            uint32_t dst = base + isF * PSTAGE + (uint32_t)(r * (PSH * 2) + c8 * 16);
            int gr = n0 + r;
            const uint32_t* src = (isF ? g_fx_bf : g_w_bf) +
                                  ((gr < nend) ? ((size_t)gr * 256 + h * 32 + c8 * 4) : 0);
            cp_async16(dst, src, (gr < nend) ? 16 : 0);
        }
        cp_commit();
    };

    if (nchunks > 0) issue(0, 0);

    for (int c = 0; c < nchunks; ++c) {
        int stg = c & 1;
        if (c + 1 < nchunks) { issue(c + 1, stg ^ 1); cp_wait<1>(); }
        else                 { cp_wait<0>(); }
        __syncthreads();

        uint32_t wbase = sb + stg * (2 * PSTAGE);
        uint32_t fbase = wbase + PSTAGE;
        int g0 = wid * 16;

#pragma unroll
        for (int s = 0; s < 4; ++s) {
            int k0 = s * 16;
            // A fragment via ldmatrix.x4.trans from [n][g] layout
            int kk = k0 + (lane & 7) + ((lane >> 4) << 3);
            int gg = g0 + (((lane >> 3) & 1) << 3);
            uint32_t af[4];
            ldm_x4t(af, wbase + (uint32_t)(kk * (PSH * 2) + gg * 2));
#pragma unroll
            for (int nt = 0; nt < 9; ++nt) {
                int kb = k0 + (lane & 15);
                uint32_t b0, b1;
                ldm_x2t(b0, b1, fbase + (uint32_t)(kb * (PSH * 2) + nt * 16));
                mma_bf16(acc[nt], af[0], af[1], af[2], af[3], b0, b1);
            }
        }
        __syncthreads();
    }

    int g = wid * 16 + grp;
#pragma unroll
    for (int nt = 0; nt < 9; ++nt) {
        int d = nt * 8 + q * 2;
        if (nt < 8) {
            atomicAdd(&g_tokens[h * 4096 + g * 64 + d], acc[nt][0]);
            atomicAdd(&g_tokens[h * 4096 + g * 64 + d + 1], acc[nt][1]);
            atomicAdd(&g_tokens[h * 4096 + (g + 8) * 64 + d], acc[nt][2]);
            atomicAdd(&g_tokens[h * 4096 + (g + 8) * 64 + d + 1], acc[nt][3]);
        } else if (q == 0) {
            atomicAdd(&g_norm[h * 64 + g], acc[nt][0]);
            atomicAdd(&g_norm[h * 64 + g + 8], acc[nt][2]);
        }
    }
}

// ---------------------------------------------------------------------------
// slice attention per head (fp32, tiny)
__global__ __launch_bounds__(256) void k_attn(
    const float* __restrict__ Wq, const float* __restrict__ Wk,
    const float* __restrict__ Wv, const float* __restrict__ Wo)
{
    __shared__ float tok[64][65];
    __shared__ float qs[64][65];
    __shared__ float ks[64][65];
    __shared__ float vs[64][65];
    __shared__ float ss[64][65];

    int h = blockIdx.x;
    int tid = threadIdx.x;
    int g = tid >> 2, q = tid & 3;

    for (int e = tid; e < 64 * 64; e += 256) {
        int gg = e >> 6, d = e & 63;
        tok[gg][d] = g_tokens[h * 4096 + e] * (1.f / (g_norm[h * 64 + gg] + EPS));
    }
    __syncthreads();

#pragma unroll
    for (int oi = 0; oi < 16; ++oi) {
        int o = q * 16 + oi;
        float sq = 0.f, sk = 0.f, sv = 0.f;
#pragma unroll
        for (int d = 0; d < 64; ++d) {
            float tv = tok[g][d];
            sq = fmaf(tv, Wq[o * 64 + d], sq);
            sk = fmaf(tv, Wk[o * 64 + d], sk);
            sv = fmaf(tv, Wv[o * 64 + d], sv);
        }
        qs[g][o] = sq; ks[g][o] = sk; vs[g][o] = sv;
    }
    __syncthreads();

    float sj[16];
    float mx = -1e30f;
#pragma unroll
    for (int ji = 0; ji < 16; ++ji) {
        int j = q * 16 + ji;
        float t = 0.f;
#pragma unroll
        for (int o = 0; o < 64; ++o) t = fmaf(qs[g][o], ks[j][o], t);
        t *= 0.125f;
        sj[ji] = t;
        mx = fmaxf(mx, t);
    }
    mx = fmaxf(mx, __shfl_xor_sync(0xffffffffu, mx, 1));
    mx = fmaxf(mx, __shfl_xor_sync(0xffffffffu, mx, 2));
    float sum = 0.f;
#pragma unroll
    for (int ji = 0; ji < 16; ++ji) { sj[ji] = __expf(sj[ji] - mx); sum += sj[ji]; }
    sum += __shfl_xor_sync(0xffffffffu, sum, 1);
    sum += __shfl_xor_sync(0xffffffffu, sum, 2);
    float inv = 1.f / sum;
#pragma unroll
    for (int ji = 0; ji < 16; ++ji) ss[g][q * 16 + ji] = sj[ji];
    __syncthreads();

#pragma unroll
    for (int di = 0; di < 16; ++di) {
        int d = q * 16 + di;
        float t = 0.f;
#pragma unroll
        for (int j = 0; j < 64; ++j) t = fmaf(ss[g][j], vs[j][d], t);
        tok[g][d] = t * inv;
    }
    __syncthreads();

#pragma unroll
    for (int oi = 0; oi < 16; ++oi) {
        int o = q * 16 + oi;
        float t = 0.f;
#pragma unroll
        for (int d = 0; d < 64; ++d) t = fmaf(tok[g][d], Wo[o * 64 + d], t);
        g_ot[h * 4096 + g * 64 + o] = t;
    }
}

// ---------------------------------------------------------------------------
// prep2: P[o][hg] = sum_d Wout[o][h*64+d] * ot[h][g][d]  -> bf16
__global__ __launch_bounds__(256) void k_prep2(const float* __restrict__ Wout) {
    __shared__ float ots[64][65];
    int h = blockIdx.x;
    int tid = threadIdx.x;
    for (int e = tid; e < 64 * 64; e += 256)
        ots[e >> 6][e & 63] = g_ot[h * 4096 + e];
    __syncthreads();
    for (int o = tid; o < 512; o += 256) {
        float wr[64];
#pragma unroll
        for (int d = 0; d < 64; ++d) wr[d] = Wout[(size_t)o * HID + h * 64 + d];
        for (int g = 0; g < 64; g += 2) {
            float s0 = 0.f, s1 = 0.f;
#pragma unroll
            for (int d = 0; d < 64; ++d) {
                s0 = fmaf(wr[d], ots[g][d], s0);
                s1 = fmaf(wr[d], ots[g + 1][d], s1);
            }
            g_P_bf[(size_t)o * 256 + h * 32 + (g >> 1)] = pk(s0, s1);
        }
    }
}

// ---------------------------------------------------------------------------
extern "C" void kernel_launch(void* const* d_in, const int* in_sizes, int n_in,
                              void* d_out, int out_size) {
    const float* x    = (const float*)d_in[0];
    const float* Wx   = (const float*)d_in[1];
    const float* bx   = (const float*)d_in[2];
    const float* Wfx  = (const float*)d_in[3];
    const float* bfx  = (const float*)d_in[4];
    const float* Ws   = (const float*)d_in[5];
    const float* bs   = (const float*)d_in[6];
    const float* temp = (const float*)d_in[7];
    const float* Wq   = (const float*)d_in[8];
    const float* Wk   = (const float*)d_in[9];
    const float* Wv   = (const float*)d_in[10];
    const float* Wo   = (const float*)d_in[11];
    const float* Wout = (const float*)d_in[12];
    const float* bout = (const float*)d_in[13];
    float* out = (float*)d_out;

    int n = in_sizes[0] / HID;
    int mtiles = (n + 127) / 128;

    uint32_t *xbf, *wfxbf, *wlsbf, *wbf, *pbf;
    float *bls;
    cudaGetSymbolAddress((void**)&xbf, g_x_bf);
    cudaGetSymbolAddress((void**)&wfxbf, g_Wfx_bf);
    cudaGetSymbolAddress((void**)&wlsbf, g_Wls_bf);
    cudaGetSymbolAddress((void**)&wbf, g_w_bf);
    cudaGetSymbolAddress((void**)&pbf, g_P_bf);
    cudaGetSymbolAddress((void**)&bls, g_bls);

    cudaFuncSetAttribute(k_gemm, cudaFuncAttributeMaxDynamicSharedMemorySize, SMEM_GEMM);

    k_zero<<<(NH * 64 * 64 + 255) / 256, 256>>>();

    int xp = n * 256;
    k_cvt<<<(xp + 255) / 256, 256>>>(x, xbf, xp);
    k_cvt<<<(512 * 256 + 255) / 256, 256>>>(Wfx, wfxbf, 512 * 256);

    dim3 gp1(4, NH);
    k_prep1<<<gp1, 256>>>(Wx, bx, Ws, bs, temp);

    // GEMM1 (mode 1): jt 0..3 logits->softmax->g_w_bf, jt 4..7 fx->g_fx_bf
    dim3 gg1(mtiles, 8);
    k_gemm<<<gg1, 256, SMEM_GEMM>>>(
        (const uint16_t*)xbf, (const uint16_t*)wlsbf, (const uint16_t*)wfxbf,
        bls, bfx, 4, 1, nullptr, 0, n);

    dim3 gpool(32, NH);
    k_pool<<<gpool, 128>>>(n);

    k_attn<<<NH, 256>>>(Wq, Wk, Wv, Wo);
    k_prep2<<<NH, 256>>>(Wout);

    // GEMM2 (mode 0): out = w @ P^T + bout
    dim3 gg2(mtiles, 4);
    k_gemm<<<gg2, 256, SMEM_GEMM>>>(
        (const uint16_t*)wbf, (const uint16_t*)pbf, (const uint16_t*)pbf,
        bout, bout, 4, 0, out, HID, n);
}